// round 1
// baseline (speedup 1.0000x reference)
#include <cuda_runtime.h>
#include <cstdint>
#include <math.h>

// ---------------------------------------------------------------------------
// Problem constants
//   B=8, H=W=64, C_cat=256, LSTM hidden=128 (gates=512), T=64, NSEQ=B*64=512
// ---------------------------------------------------------------------------

#define EPS_BN 1e-5f

// ------------------------- scratch (device globals) ------------------------
__device__ float g_seq [32768u * 256u];          // rows-LSTM input, NHWC of concat ; later conv temp
__device__ float g_xg  [33554432u];              // 32768 x 1024 (fwd gates | bwd gates)
__device__ float g_rows[32768u * 256u];          // rows-LSTM output, layout [b][w][h][c] == cols seq
__device__ float g_cols[8u * 256u * 64u * 64u];  // cols-LSTM output, NCHW
__device__ float g_t1  [8u * 256u * 64u * 64u];
__device__ float g_t2  [8u * 256u * 64u * 64u];
__device__ float g_wfold[256u * 256u * 9u];      // folded c2_w1 (duplicated-channel concat)
__device__ float g_whhT[2][128 * 512];           // [dir][k][gate]
__device__ float g_bias2[2][512];                // bih+bhh per dir

// ---------------------------------------------------------------------------
// prep: Whh transpose, bias sums, fold c2_w1 over duplicated channels
// ---------------------------------------------------------------------------
__global__ void prep_kernel(const float* __restrict__ whh_f, const float* __restrict__ whh_b,
                            const float* __restrict__ bih_f, const float* __restrict__ bhh_f,
                            const float* __restrict__ bih_b, const float* __restrict__ bhh_b,
                            const float* __restrict__ c2w1)
{
    int i = blockIdx.x * blockDim.x + threadIdx.x;
    if (i < 512 * 128) {
        int g = i / 128, k = i % 128;
        g_whhT[0][k * 512 + g] = whh_f[i];
        g_whhT[1][k * 512 + g] = whh_b[i];
    }
    if (i < 512) {
        g_bias2[0][i] = bih_f[i] + bhh_f[i];
        g_bias2[1][i] = bih_b[i] + bhh_b[i];
    }
    if (i < 256 * 256 * 9) {
        int r = i % 9;
        int c = (i / 9) % 256;
        int oc = i / (9 * 256);
        g_wfold[i] = c2w1[((size_t)oc * 512 + c) * 9 + r]
                   + c2w1[((size_t)oc * 512 + c + 256) * 9 + r];
    }
}

// ---------------------------------------------------------------------------
// build seq (NHWC of concat(x2, up2x(x1))) with transpose through shared mem
// grid: (512 bh, 8 ctile), 256 threads
// ---------------------------------------------------------------------------
__global__ __launch_bounds__(256) void build_seq_kernel(const float* __restrict__ x2,
                                                        const float* __restrict__ x1)
{
    __shared__ float sh[32][65];
    int bh = blockIdx.x;            // b*64 + h
    int b = bh >> 6, h = bh & 63;
    int ct = blockIdx.y;
    int c0 = ct * 32;
    int tid = threadIdx.x;

    if (ct < 4) {
        for (int idx = tid; idx < 32 * 64; idx += 256) {
            int ci = idx >> 6, w = idx & 63;
            sh[ci][w] = x2[(((size_t)b * 128 + (c0 + ci)) * 64 + h) * 64 + w];
        }
    } else {
        int cc0 = c0 - 128;
        float py = (float)h * 31.0f / 63.0f;
        int yl = (int)floorf(py);
        float wy = py - (float)yl;
        int yh = min(yl + 1, 31);
        for (int idx = tid; idx < 32 * 64; idx += 256) {
            int ci = idx >> 6, w = idx & 63;
            float px = (float)w * 31.0f / 63.0f;
            int xl = (int)floorf(px);
            float wx = px - (float)xl;
            int xh = min(xl + 1, 31);
            const float* base = x1 + ((size_t)b * 128 + (cc0 + ci)) * 1024;
            float v00 = base[yl * 32 + xl], v01 = base[yl * 32 + xh];
            float v10 = base[yh * 32 + xl], v11 = base[yh * 32 + xh];
            float v0 = v00 * (1.f - wx) + v01 * wx;
            float v1 = v10 * (1.f - wx) + v11 * wx;
            sh[ci][w] = v0 * (1.f - wy) + v1 * wy;
        }
    }
    __syncthreads();
    for (int idx = tid; idx < 32 * 64; idx += 256) {
        int w = idx >> 5, cl = idx & 31;
        g_seq[((size_t)bh * 64 + w) * 256 + c0 + cl] = sh[cl][w];
    }
}

// ---------------------------------------------------------------------------
// GEMM: xg[32768, 1024] = A[32768, 256] @ [Wih_f ; Wih_b]^T + bias
// mode 0: A = g_seq (rows pass), mode 1: A = g_rows (cols pass)
// block tile 64x64, 256 threads, 4x4 register tile
// ---------------------------------------------------------------------------
__global__ __launch_bounds__(256) void gemm_xg_kernel(int mode,
                                                      const float* __restrict__ wih_f,
                                                      const float* __restrict__ wih_b)
{
    const float* A = mode ? g_rows : g_seq;
    int mbase = blockIdx.x * 64;
    int nbase = blockIdx.y * 64;
    const float* Wg;
    const float* bias;
    int nloc;
    if (nbase < 512) { Wg = wih_f; bias = g_bias2[0]; nloc = nbase; }
    else             { Wg = wih_b; bias = g_bias2[1]; nloc = nbase - 512; }

    __shared__ float a_sh[16][68];
    __shared__ float b_sh[16][68];

    int tid = threadIdx.x;
    int tm = tid >> 4, tn = tid & 15;
    float acc[4][4];
#pragma unroll
    for (int i = 0; i < 4; i++)
#pragma unroll
        for (int j = 0; j < 4; j++) acc[i][j] = 0.f;

    int lm = tid >> 2;            // 0..63
    int lk = (tid & 3) * 4;       // 0,4,8,12

    for (int k0 = 0; k0 < 256; k0 += 16) {
        float4 va = *(const float4*)&A [((size_t)(mbase + lm)) * 256 + k0 + lk];
        float4 vb = *(const float4*)&Wg[((size_t)(nloc + lm)) * 256 + k0 + lk];
        a_sh[lk + 0][lm] = va.x; a_sh[lk + 1][lm] = va.y;
        a_sh[lk + 2][lm] = va.z; a_sh[lk + 3][lm] = va.w;
        b_sh[lk + 0][lm] = vb.x; b_sh[lk + 1][lm] = vb.y;
        b_sh[lk + 2][lm] = vb.z; b_sh[lk + 3][lm] = vb.w;
        __syncthreads();
#pragma unroll
        for (int k = 0; k < 16; k++) {
            float4 a4 = *(const float4*)&a_sh[k][tm * 4];
            float4 b4 = *(const float4*)&b_sh[k][tn * 4];
            float av[4] = {a4.x, a4.y, a4.z, a4.w};
            float bv[4] = {b4.x, b4.y, b4.z, b4.w};
#pragma unroll
            for (int i = 0; i < 4; i++)
#pragma unroll
                for (int j = 0; j < 4; j++) acc[i][j] += av[i] * bv[j];
        }
        __syncthreads();
    }
#pragma unroll
    for (int i = 0; i < 4; i++) {
        size_t row = (size_t)(mbase + tm * 4 + i) * 1024 + nbase + tn * 4;
#pragma unroll
        for (int j = 0; j < 4; j++)
            g_xg[row + j] = acc[i][j] + bias[nloc + tn * 4 + j];
    }
}

// ---------------------------------------------------------------------------
// LSTM recurrence. grid = 128 blocks (dir = blk>>6), 256 threads.
// Each block owns 8 sequences; 64 steps inside the kernel.
// Phase 1: gates[8][512] = xg + h[8][128] @ WhhT  (4seq x 4gate per thread)
// Phase 2: activations + state update + output write
// mode 0: rows pass (out g_rows, layout [b][w][h][c])
// mode 1: cols pass (out g_cols, NCHW)
// ---------------------------------------------------------------------------
__global__ __launch_bounds__(256) void lstm_kernel(int mode)
{
    int dir = blockIdx.x >> 6;
    int blk = blockIdx.x & 63;
    const float* whhT = g_whhT[dir];
    const float* xg = g_xg + dir * 512;
    float* out = mode ? g_cols : g_rows;

    __shared__ float h_sh[8][132];
    __shared__ float g_sh[8][516];

    int tid = threadIdx.x;
    int ts = tid >> 7;           // 0..1
    int tg = tid & 127;
    int g0 = tg * 4;
    int s_base = ts * 4;
    int base_n = blk * 8;

    float c_reg[4] = {0.f, 0.f, 0.f, 0.f};

    for (int t = 0; t < 64; t++) {
        int ta = dir ? (63 - t) : t;
        float acc[4][4];
#pragma unroll
        for (int si = 0; si < 4; si++) {
            int n = base_n + s_base + si;
            float4 v = *(const float4*)&xg[((size_t)n * 64 + ta) * 1024 + g0];
            acc[si][0] = v.x; acc[si][1] = v.y; acc[si][2] = v.z; acc[si][3] = v.w;
        }
        if (t > 0) {
#pragma unroll 4
            for (int k = 0; k < 128; k++) {
                float4 w = *(const float4*)&whhT[(k << 9) + g0];
                float h0 = h_sh[s_base + 0][k];
                float h1 = h_sh[s_base + 1][k];
                float h2 = h_sh[s_base + 2][k];
                float h3 = h_sh[s_base + 3][k];
                acc[0][0] += h0 * w.x; acc[0][1] += h0 * w.y; acc[0][2] += h0 * w.z; acc[0][3] += h0 * w.w;
                acc[1][0] += h1 * w.x; acc[1][1] += h1 * w.y; acc[1][2] += h1 * w.z; acc[1][3] += h1 * w.w;
                acc[2][0] += h2 * w.x; acc[2][1] += h2 * w.y; acc[2][2] += h2 * w.z; acc[2][3] += h2 * w.w;
                acc[3][0] += h3 * w.x; acc[3][1] += h3 * w.y; acc[3][2] += h3 * w.z; acc[3][3] += h3 * w.w;
            }
        }
#pragma unroll
        for (int si = 0; si < 4; si++) {
            *(float4*)&g_sh[s_base + si][g0] =
                make_float4(acc[si][0], acc[si][1], acc[si][2], acc[si][3]);
        }
        __syncthreads();
#pragma unroll
        for (int p = 0; p < 4; p++) {
            int idx = tid + p * 256;
            int s = idx >> 7, j = idx & 127;
            float iv = g_sh[s][j];
            float fv = g_sh[s][128 + j];
            float gv = g_sh[s][256 + j];
            float ov = g_sh[s][384 + j];
            float ig = 1.f / (1.f + expf(-iv));
            float fg = 1.f / (1.f + expf(-fv));
            float og = 1.f / (1.f + expf(-ov));
            c_reg[p] = fg * c_reg[p] + ig * tanhf(gv);
            float h = og * tanhf(c_reg[p]);
            h_sh[s][j] = h;
            int n = base_n + s;
            int b = n >> 6, loc = n & 63;
            size_t oidx;
            if (mode == 0)
                oidx = (((size_t)(b * 64 + ta)) * 64 + loc) * 256 + dir * 128 + j;
            else
                oidx = (((size_t)b * 256 + dir * 128 + j) * 64 + ta) * 64 + loc;
            out[oidx] = h;
        }
        __syncthreads();
    }
}

// ---------------------------------------------------------------------------
// Direct 3x3 SAME conv, NCHW, fused scale=g/sqrt(1+eps), bias, ReLU.
// Supports split input (in0 has C0 channels, in1 the next C1) for concat.
// Block: one (b, y) output row x 64 output channels. 128 threads.
// Thread: 4 oc x 8 px register tile. cin chunk = 8.
// ---------------------------------------------------------------------------
__global__ __launch_bounds__(128) void conv3x3_kernel(
    const float* __restrict__ in0, int C0,
    const float* __restrict__ in1, int C1,
    const float* __restrict__ Wt,
    const float* __restrict__ gamma, const float* __restrict__ beta,
    float* __restrict__ out, int OC)
{
    __shared__ float w_sh[72][65];      // [kc*9 + r*3+s][oc]
    __shared__ float in_sh[8][3][68];

    int by = blockIdx.x;
    int b = by >> 6, y = by & 63;
    int ocb = blockIdx.y * 64;
    int CIN = C0 + C1;

    int tid = threadIdx.x;
    int tx = tid & 7;       // px group
    int to = tid >> 3;      // oc group
    int x0 = tx * 8;
    int oc0 = to * 4;

    float acc[4][8];
#pragma unroll
    for (int o = 0; o < 4; o++)
#pragma unroll
        for (int i = 0; i < 8; i++) acc[o][i] = 0.f;

    for (int c0 = 0; c0 < CIN; c0 += 8) {
        // --- load input rows (8 cin x 3 rows x 66 cols, zero-padded halo) ---
        for (int idx = tid; idx < 8 * 3 * 66; idx += 128) {
            int kc = idx / 198;
            int rem = idx % 198;
            int r = rem / 66;
            int xx = rem % 66;
            int yy = y + r - 1;
            int xglob = xx - 1;
            float v = 0.f;
            if ((unsigned)yy < 64u && (unsigned)xglob < 64u) {
                int c = c0 + kc;
                const float* src = (c < C0)
                    ? (in0 + (((size_t)b * C0 + c) * 64 + yy) * 64)
                    : (in1 + (((size_t)b * C1 + (c - C0)) * 64 + yy) * 64);
                v = src[xglob];
            }
            in_sh[kc][r][xx] = v;
        }
        // --- load weights (64 oc x 8 cin x 9), coalesced read, scattered STS ---
        for (int idx = tid; idx < 64 * 8 * 9; idx += 128) {
            int rr = idx % 9;
            int kc = (idx / 9) & 7;
            int o = idx / 72;
            w_sh[kc * 9 + rr][o] = Wt[(((size_t)(ocb + o)) * CIN + c0 + kc) * 9 + rr];
        }
        __syncthreads();

        for (int kc = 0; kc < 8; kc++) {
#pragma unroll
            for (int r = 0; r < 3; r++) {
                float4 va = *(const float4*)&in_sh[kc][r][x0];
                float4 vb = *(const float4*)&in_sh[kc][r][x0 + 4];
                float v8 = in_sh[kc][r][x0 + 8];
                float v9 = in_sh[kc][r][x0 + 9];
                float v[10] = {va.x, va.y, va.z, va.w, vb.x, vb.y, vb.z, vb.w, v8, v9};
#pragma unroll
                for (int s = 0; s < 3; s++) {
#pragma unroll
                    for (int o = 0; o < 4; o++) {
                        float wv = w_sh[kc * 9 + r * 3 + s][oc0 + o];
#pragma unroll
                        for (int i = 0; i < 8; i++)
                            acc[o][i] += wv * v[s + i];
                    }
                }
            }
        }
        __syncthreads();
    }

#pragma unroll
    for (int o = 0; o < 4; o++) {
        int oc = ocb + oc0 + o;
        float sc = gamma[oc] * rsqrtf(1.0f + EPS_BN);
        float bb = beta[oc];
        float ov[8];
#pragma unroll
        for (int i = 0; i < 8; i++)
            ov[i] = fmaxf(acc[o][i] * sc + bb, 0.f);
        float* dst = out + (((size_t)b * OC + oc) * 64 + y) * 64 + x0;
        *(float4*)dst       = make_float4(ov[0], ov[1], ov[2], ov[3]);
        *(float4*)(dst + 4) = make_float4(ov[4], ov[5], ov[6], ov[7]);
    }
}

// ---------------------------------------------------------------------------
// launcher
// ---------------------------------------------------------------------------
extern "C" void kernel_launch(void* const* d_in, const int* in_sizes, int n_in,
                              void* d_out, int out_size)
{
    const float* x1       = (const float*)d_in[0];
    const float* x2       = (const float*)d_in[1];
    const float* wih_f    = (const float*)d_in[2];
    const float* whh_f    = (const float*)d_in[3];
    const float* bih_f    = (const float*)d_in[4];
    const float* bhh_f    = (const float*)d_in[5];
    const float* wih_b    = (const float*)d_in[6];
    const float* whh_b    = (const float*)d_in[7];
    const float* bih_b    = (const float*)d_in[8];
    const float* bhh_b    = (const float*)d_in[9];
    const float* c2_w1    = (const float*)d_in[10];
    const float* c2_g1    = (const float*)d_in[11];
    const float* c2_b1    = (const float*)d_in[12];
    const float* c2_w2    = (const float*)d_in[13];
    const float* c2_g2    = (const float*)d_in[14];
    const float* c2_b2    = (const float*)d_in[15];
    const float* cv_w1    = (const float*)d_in[16];
    const float* cv_g1    = (const float*)d_in[17];
    const float* cv_b1    = (const float*)d_in[18];
    const float* cv_w2    = (const float*)d_in[19];
    const float* cv_g2    = (const float*)d_in[20];
    const float* cv_b2    = (const float*)d_in[21];

    float *p_cols = nullptr, *p_t1 = nullptr, *p_t2 = nullptr, *p_seq = nullptr, *p_wfold = nullptr;
    cudaGetSymbolAddress((void**)&p_cols, g_cols);
    cudaGetSymbolAddress((void**)&p_t1, g_t1);
    cudaGetSymbolAddress((void**)&p_t2, g_t2);
    cudaGetSymbolAddress((void**)&p_seq, g_seq);
    cudaGetSymbolAddress((void**)&p_wfold, g_wfold);

    // 1. prep (Whh transpose, bias sums, folded first-conv weights)
    prep_kernel<<<2304, 256>>>(whh_f, whh_b, bih_f, bhh_f, bih_b, bhh_b, c2_w1);

    // 2. build rows-sequence (upsample + concat, NHWC)
    build_seq_kernel<<<dim3(512, 8), 256>>>(x2, x1);

    // 3. rows pass: input-gate GEMM (both dirs), then recurrence
    gemm_xg_kernel<<<dim3(512, 16), 256>>>(0, wih_f, wih_b);
    lstm_kernel<<<128, 256>>>(0);

    // 4. cols pass: g_rows layout is exactly the cols sequence matrix
    gemm_xg_kernel<<<dim3(512, 16), 256>>>(1, wih_f, wih_b);
    lstm_kernel<<<128, 256>>>(1);

    // 5. x_site = double_conv(concat([x,x])) via folded weights
    conv3x3_kernel<<<dim3(512, 4), 128>>>(p_cols, 256, nullptr, 0, p_wfold, c2_g1, c2_b1, p_t1, 256);
    conv3x3_kernel<<<dim3(512, 4), 128>>>(p_t1, 256, nullptr, 0, c2_w2, c2_g2, c2_b2, p_t2, 256);

    // 6. x = double_conv(concat([x, x_site]))
    conv3x3_kernel<<<dim3(512, 4), 128>>>(p_cols, 256, p_t2, 256, c2_w1, c2_g1, c2_b1, p_t1, 256);
    conv3x3_kernel<<<dim3(512, 4), 128>>>(p_t1, 256, nullptr, 0, c2_w2, c2_g2, c2_b2, p_seq, 256);

    // 7. final double_conv (cv): 256->128, 128->128 -> d_out
    conv3x3_kernel<<<dim3(512, 2), 128>>>(p_seq, 256, nullptr, 0, cv_w1, cv_g1, cv_b1, p_t2, 128);
    conv3x3_kernel<<<dim3(512, 2), 128>>>(p_t2, 128, nullptr, 0, cv_w2, cv_g2, cv_b2, (float*)d_out, 128);
}

// round 4
// speedup vs baseline: 1.0182x; 1.0182x over previous
#include <cuda_runtime.h>
#include <cstdint>
#include <math.h>

#define EPS_BN 1e-5f

// ------------------------- scratch (device globals) ------------------------
__device__ float g_seq [32768u * 256u];          // rows-LSTM input NHWC; later conv temp
__device__ float g_xg  [33554432u];              // 32768 x 1024
__device__ float g_rows[32768u * 256u];          // rows-LSTM out [b][w][h][c] == cols seq
__device__ float g_cols[8u * 256u * 64u * 64u];  // cols-LSTM out, NCHW
__device__ float g_t1  [8u * 256u * 64u * 64u];
__device__ float g_t2  [8u * 256u * 64u * 64u];
__device__ float g_wfold[256u * 256u * 9u];
__device__ float g_whhT[2][128 * 512];
__device__ float g_bias2[2][512];

// ---------------------------------------------------------------------------
__global__ void prep_kernel(const float* __restrict__ whh_f, const float* __restrict__ whh_b,
                            const float* __restrict__ bih_f, const float* __restrict__ bhh_f,
                            const float* __restrict__ bih_b, const float* __restrict__ bhh_b,
                            const float* __restrict__ c2w1)
{
    int i = blockIdx.x * blockDim.x + threadIdx.x;
    if (i < 512 * 128) {
        int g = i / 128, k = i % 128;
        g_whhT[0][k * 512 + g] = whh_f[i];
        g_whhT[1][k * 512 + g] = whh_b[i];
    }
    if (i < 512) {
        g_bias2[0][i] = bih_f[i] + bhh_f[i];
        g_bias2[1][i] = bih_b[i] + bhh_b[i];
    }
    if (i < 256 * 256 * 9) {
        int r = i % 9;
        int c = (i / 9) % 256;
        int oc = i / (9 * 256);
        g_wfold[i] = c2w1[((size_t)oc * 512 + c) * 9 + r]
                   + c2w1[((size_t)oc * 512 + c + 256) * 9 + r];
    }
}

// ---------------------------------------------------------------------------
__global__ __launch_bounds__(256) void build_seq_kernel(const float* __restrict__ x2,
                                                        const float* __restrict__ x1)
{
    __shared__ float sh[32][65];
    int bh = blockIdx.x;
    int b = bh >> 6, h = bh & 63;
    int ct = blockIdx.y;
    int c0 = ct * 32;
    int tid = threadIdx.x;

    if (ct < 4) {
        for (int idx = tid; idx < 32 * 64; idx += 256) {
            int ci = idx >> 6, w = idx & 63;
            sh[ci][w] = x2[(((size_t)b * 128 + (c0 + ci)) * 64 + h) * 64 + w];
        }
    } else {
        int cc0 = c0 - 128;
        float py = (float)h * 31.0f / 63.0f;
        int yl = (int)floorf(py);
        float wy = py - (float)yl;
        int yh = min(yl + 1, 31);
        for (int idx = tid; idx < 32 * 64; idx += 256) {
            int ci = idx >> 6, w = idx & 63;
            float px = (float)w * 31.0f / 63.0f;
            int xl = (int)floorf(px);
            float wx = px - (float)xl;
            int xh = min(xl + 1, 31);
            const float* base = x1 + ((size_t)b * 128 + (cc0 + ci)) * 1024;
            float v00 = base[yl * 32 + xl], v01 = base[yl * 32 + xh];
            float v10 = base[yh * 32 + xl], v11 = base[yh * 32 + xh];
            float v0 = v00 * (1.f - wx) + v01 * wx;
            float v1 = v10 * (1.f - wx) + v11 * wx;
            sh[ci][w] = v0 * (1.f - wy) + v1 * wy;
        }
    }
    __syncthreads();
    for (int idx = tid; idx < 32 * 64; idx += 256) {
        int w = idx >> 5, cl = idx & 31;
        g_seq[((size_t)bh * 64 + w) * 256 + c0 + cl] = sh[cl][w];
    }
}

// ---------------------------------------------------------------------------
// GEMM: xg[32768,1024] = A[32768,256] @ [Wih_f;Wih_b]^T + bias
// block tile 128x64, 256 threads, 8x4 register tile.
// ---------------------------------------------------------------------------
__global__ __launch_bounds__(256) void gemm_xg_kernel(int mode,
                                                      const float* __restrict__ wih_f,
                                                      const float* __restrict__ wih_b)
{
    const float* A = mode ? g_rows : g_seq;
    int mbase = blockIdx.x * 128;
    int nbase = blockIdx.y * 64;
    const float* Wg;
    const float* bias;
    int nloc;
    if (nbase < 512) { Wg = wih_f; bias = g_bias2[0]; nloc = nbase; }
    else             { Wg = wih_b; bias = g_bias2[1]; nloc = nbase - 512; }

    __shared__ __align__(16) float a_sh[16][132];
    __shared__ __align__(16) float b_sh[16][68];

    int tid = threadIdx.x;
    int tm = tid >> 4;          // 0..15 -> rows tm*8
    int tn = tid & 15;          // cols tn*4

    int lma = tid >> 1;         // 0..127
    int lka = (tid & 1) * 8;    // 0 or 8
    int lmb = tid >> 2;         // 0..63
    int lkb = (tid & 3) * 4;    // 0,4,8,12

    float acc[8][4];
#pragma unroll
    for (int i = 0; i < 8; i++)
#pragma unroll
        for (int j = 0; j < 4; j++) acc[i][j] = 0.f;

    for (int k0 = 0; k0 < 256; k0 += 16) {
        float4 va0 = *(const float4*)&A [((size_t)(mbase + lma)) * 256 + k0 + lka];
        float4 va1 = *(const float4*)&A [((size_t)(mbase + lma)) * 256 + k0 + lka + 4];
        float4 vb  = *(const float4*)&Wg[((size_t)(nloc + lmb)) * 256 + k0 + lkb];
        a_sh[lka + 0][lma] = va0.x; a_sh[lka + 1][lma] = va0.y;
        a_sh[lka + 2][lma] = va0.z; a_sh[lka + 3][lma] = va0.w;
        a_sh[lka + 4][lma] = va1.x; a_sh[lka + 5][lma] = va1.y;
        a_sh[lka + 6][lma] = va1.z; a_sh[lka + 7][lma] = va1.w;
        b_sh[lkb + 0][lmb] = vb.x;  b_sh[lkb + 1][lmb] = vb.y;
        b_sh[lkb + 2][lmb] = vb.z;  b_sh[lkb + 3][lmb] = vb.w;
        __syncthreads();
#pragma unroll
        for (int k = 0; k < 16; k++) {
            float4 a0 = *(const float4*)&a_sh[k][tm * 8];
            float4 a1 = *(const float4*)&a_sh[k][tm * 8 + 4];
            float4 b4 = *(const float4*)&b_sh[k][tn * 4];
            float av[8] = {a0.x, a0.y, a0.z, a0.w, a1.x, a1.y, a1.z, a1.w};
            float bv[4] = {b4.x, b4.y, b4.z, b4.w};
#pragma unroll
            for (int i = 0; i < 8; i++)
#pragma unroll
                for (int j = 0; j < 4; j++) acc[i][j] += av[i] * bv[j];
        }
        __syncthreads();
    }
    float4 bb = *(const float4*)&bias[nloc + tn * 4];
    float bv[4] = {bb.x, bb.y, bb.z, bb.w};
#pragma unroll
    for (int i = 0; i < 8; i++) {
        float* dst = &g_xg[(size_t)(mbase + tm * 8 + i) * 1024 + nbase + tn * 4];
        *(float4*)dst = make_float4(acc[i][0] + bv[0], acc[i][1] + bv[1],
                                    acc[i][2] + bv[2], acc[i][3] + bv[3]);
    }
}

// ---------------------------------------------------------------------------
// LSTM recurrence. grid = 128 (dir = blk>>6), 512 threads (16 warps).
// Each block owns 8 sequences, 64 steps.
// Gate phase: thread = 2 seq x 4 gates. Activation: thread = 2 cells.
// ---------------------------------------------------------------------------
__global__ __launch_bounds__(512) void lstm_kernel(int mode)
{
    int dir = blockIdx.x >> 6;
    int blk = blockIdx.x & 63;
    const float* whhT = g_whhT[dir];
    const float* xg = g_xg + dir * 512;
    float* out = mode ? g_cols : g_rows;

    __shared__ __align__(16) float h_sh[8][132];
    __shared__ __align__(16) float g_sh[8][516];

    int tid = threadIdx.x;
    int ts = tid >> 7;           // 0..3
    int tg = tid & 127;
    int g0 = tg * 4;
    int sb = ts * 2;             // 2 sequences per thread
    int base_n = blk * 8;

    float c_reg[2] = {0.f, 0.f};

    for (int t = 0; t < 64; t++) {
        int ta = dir ? (63 - t) : t;
        float acc[2][4];
#pragma unroll
        for (int si = 0; si < 2; si++) {
            int n = base_n + sb + si;
            float4 v = *(const float4*)&xg[((size_t)n * 64 + ta) * 1024 + g0];
            acc[si][0] = v.x; acc[si][1] = v.y; acc[si][2] = v.z; acc[si][3] = v.w;
        }
        if (t > 0) {
#pragma unroll 4
            for (int k = 0; k < 128; k++) {
                float4 w = *(const float4*)&whhT[(k << 9) + g0];
                float h0 = h_sh[sb + 0][k];
                float h1 = h_sh[sb + 1][k];
                acc[0][0] += h0 * w.x; acc[0][1] += h0 * w.y;
                acc[0][2] += h0 * w.z; acc[0][3] += h0 * w.w;
                acc[1][0] += h1 * w.x; acc[1][1] += h1 * w.y;
                acc[1][2] += h1 * w.z; acc[1][3] += h1 * w.w;
            }
        }
#pragma unroll
        for (int si = 0; si < 2; si++) {
            *(float4*)&g_sh[sb + si][g0] =
                make_float4(acc[si][0], acc[si][1], acc[si][2], acc[si][3]);
        }
        __syncthreads();
#pragma unroll
        for (int p = 0; p < 2; p++) {
            int idx = tid + p * 512;
            int s = idx >> 7, j = idx & 127;
            float iv = g_sh[s][j];
            float fv = g_sh[s][128 + j];
            float gv = g_sh[s][256 + j];
            float ov = g_sh[s][384 + j];
            float ig = 1.f / (1.f + expf(-iv));
            float fg = 1.f / (1.f + expf(-fv));
            float og = 1.f / (1.f + expf(-ov));
            c_reg[p] = fg * c_reg[p] + ig * tanhf(gv);
            float h = og * tanhf(c_reg[p]);
            h_sh[s][j] = h;
            int n = base_n + s;
            int b = n >> 6, loc = n & 63;
            size_t oidx;
            if (mode == 0)
                oidx = (((size_t)(b * 64 + ta)) * 64 + loc) * 256 + dir * 128 + j;
            else
                oidx = (((size_t)b * 256 + dir * 128 + j) * 64 + ta) * 64 + loc;
            out[oidx] = h;
        }
        __syncthreads();
    }
}

// ---------------------------------------------------------------------------
// Direct 3x3 SAME conv, NCHW, fused BN-scale + bias + ReLU (scalar FFMA).
// Block: one (b,y) row x 64 oc. 128 threads, thread = 4 oc x 8 px.
// Weights in shared with oc contiguous -> one LDS.128 feeds 4 oc.
// ---------------------------------------------------------------------------
__global__ __launch_bounds__(128) void conv3x3_kernel(
    const float* __restrict__ in0, int C0,
    const float* __restrict__ in1, int C1,
    const float* __restrict__ Wt,
    const float* __restrict__ gamma, const float* __restrict__ beta,
    float* __restrict__ out, int OC)
{
    __shared__ __align__(16) float w_sh[72][68];     // [kc*9 + r*3+s][oc]
    __shared__ __align__(16) float in_sh[8][3][68];

    int by = blockIdx.x;
    int b = by >> 6, y = by & 63;
    int ocb = blockIdx.y * 64;
    int CIN = C0 + C1;

    int tid = threadIdx.x;
    int tx = tid & 7;
    int to = tid >> 3;
    int x0 = tx * 8;
    int oc0 = to * 4;

    float acc[4][8];
#pragma unroll
    for (int o = 0; o < 4; o++)
#pragma unroll
        for (int i = 0; i < 8; i++) acc[o][i] = 0.f;

    for (int c0 = 0; c0 < CIN; c0 += 8) {
        // input rows (8 cin x 3 rows x 66 cols, zero halo)
        for (int idx = tid; idx < 8 * 3 * 66; idx += 128) {
            int kc = idx / 198;
            int rem = idx % 198;
            int r = rem / 66;
            int xx = rem % 66;
            int yy = y + r - 1;
            int xglob = xx - 1;
            float v = 0.f;
            if ((unsigned)yy < 64u && (unsigned)xglob < 64u) {
                int c = c0 + kc;
                const float* src = (c < C0)
                    ? (in0 + (((size_t)b * C0 + c) * 64 + yy) * 64)
                    : (in1 + (((size_t)b * C1 + (c - C0)) * 64 + yy) * 64);
                v = src[xglob];
            }
            in_sh[kc][r][xx] = v;
        }
        // weights: 64 oc x 8 cin x 9
        const float* wbase = Wt + ((size_t)ocb * CIN + c0) * 9;
        for (int idx = tid; idx < 64 * 8 * 9; idx += 128) {
            int rr = idx % 9;
            int kc = (idx / 9) & 7;
            int o = idx / 72;
            w_sh[kc * 9 + rr][o] = wbase[((size_t)o * CIN + kc) * 9 + rr];
        }
        __syncthreads();

#pragma unroll 2
        for (int kc = 0; kc < 8; kc++) {
#pragma unroll
            for (int r = 0; r < 3; r++) {
                const float* rowp = &in_sh[kc][r][x0];
                float4 va = *(const float4*)rowp;
                float4 vb = *(const float4*)(rowp + 4);
                float v8 = rowp[8];
                float v9 = rowp[9];
                float v[10] = {va.x, va.y, va.z, va.w, vb.x, vb.y, vb.z, vb.w, v8, v9};
#pragma unroll
                for (int s = 0; s < 3; s++) {
                    float4 w4 = *(const float4*)&w_sh[kc * 9 + r * 3 + s][oc0];
                    float wv[4] = {w4.x, w4.y, w4.z, w4.w};
#pragma unroll
                    for (int o = 0; o < 4; o++)
#pragma unroll
                        for (int i = 0; i < 8; i++)
                            acc[o][i] += wv[o] * v[s + i];
                }
            }
        }
        __syncthreads();
    }

#pragma unroll
    for (int o = 0; o < 4; o++) {
        int oc = ocb + oc0 + o;
        float sc = gamma[oc] * rsqrtf(1.0f + EPS_BN);
        float bb = beta[oc];
        float ov[8];
#pragma unroll
        for (int i = 0; i < 8; i++)
            ov[i] = fmaxf(acc[o][i] * sc + bb, 0.f);
        float* dst = out + (((size_t)b * OC + oc) * 64 + y) * 64 + x0;
        *(float4*)dst       = make_float4(ov[0], ov[1], ov[2], ov[3]);
        *(float4*)(dst + 4) = make_float4(ov[4], ov[5], ov[6], ov[7]);
    }
}

// ---------------------------------------------------------------------------
extern "C" void kernel_launch(void* const* d_in, const int* in_sizes, int n_in,
                              void* d_out, int out_size)
{
    const float* x1       = (const float*)d_in[0];
    const float* x2       = (const float*)d_in[1];
    const float* wih_f    = (const float*)d_in[2];
    const float* whh_f    = (const float*)d_in[3];
    const float* bih_f    = (const float*)d_in[4];
    const float* bhh_f    = (const float*)d_in[5];
    const float* wih_b    = (const float*)d_in[6];
    const float* whh_b    = (const float*)d_in[7];
    const float* bih_b    = (const float*)d_in[8];
    const float* bhh_b    = (const float*)d_in[9];
    const float* c2_w1    = (const float*)d_in[10];
    const float* c2_g1    = (const float*)d_in[11];
    const float* c2_b1    = (const float*)d_in[12];
    const float* c2_w2    = (const float*)d_in[13];
    const float* c2_g2    = (const float*)d_in[14];
    const float* c2_b2    = (const float*)d_in[15];
    const float* cv_w1    = (const float*)d_in[16];
    const float* cv_g1    = (const float*)d_in[17];
    const float* cv_b1    = (const float*)d_in[18];
    const float* cv_w2    = (const float*)d_in[19];
    const float* cv_g2    = (const float*)d_in[20];
    const float* cv_b2    = (const float*)d_in[21];

    float *p_cols = nullptr, *p_t1 = nullptr, *p_t2 = nullptr, *p_seq = nullptr, *p_wfold = nullptr;
    cudaGetSymbolAddress((void**)&p_cols, g_cols);
    cudaGetSymbolAddress((void**)&p_t1, g_t1);
    cudaGetSymbolAddress((void**)&p_t2, g_t2);
    cudaGetSymbolAddress((void**)&p_seq, g_seq);
    cudaGetSymbolAddress((void**)&p_wfold, g_wfold);

    prep_kernel<<<2304, 256>>>(whh_f, whh_b, bih_f, bhh_f, bih_b, bhh_b, c2_w1);
    build_seq_kernel<<<dim3(512, 8), 256>>>(x2, x1);

    gemm_xg_kernel<<<dim3(256, 16), 256>>>(0, wih_f, wih_b);
    lstm_kernel<<<128, 512>>>(0);

    gemm_xg_kernel<<<dim3(256, 16), 256>>>(1, wih_f, wih_b);
    lstm_kernel<<<128, 512>>>(1);

    conv3x3_kernel<<<dim3(512, 4), 128>>>(p_cols, 256, nullptr, 0, p_wfold, c2_g1, c2_b1, p_t1, 256);
    conv3x3_kernel<<<dim3(512, 4), 128>>>(p_t1, 256, nullptr, 0, c2_w2, c2_g2, c2_b2, p_t2, 256);

    conv3x3_kernel<<<dim3(512, 4), 128>>>(p_cols, 256, p_t2, 256, c2_w1, c2_g1, c2_b1, p_t1, 256);
    conv3x3_kernel<<<dim3(512, 4), 128>>>(p_t1, 256, nullptr, 0, c2_w2, c2_g2, c2_b2, p_seq, 256);

    conv3x3_kernel<<<dim3(512, 2), 128>>>(p_seq, 256, nullptr, 0, cv_w1, cv_g1, cv_b1, p_t2, 128);
    conv3x3_kernel<<<dim3(512, 2), 128>>>(p_t2, 128, nullptr, 0, cv_w2, cv_g2, cv_b2, (float*)d_out, 128);
}

// round 7
// speedup vs baseline: 1.8706x; 1.8371x over previous
#include <cuda_runtime.h>
#include <cuda_bf16.h>
#include <cstdint>
#include <math.h>

#define EPS_BN 1e-5f

// ===========================================================================
// scratch (device globals)
// ===========================================================================
__device__ float    g_seq [8388608];      // rows-LSTM input NHWC fp32
__device__ float    g_xg  [33554432];     // 32768 x 1024
__device__ float    g_rows[8388608];      // rows-LSTM out [b][w][h][c] fp32
__device__ uint32_t g_cols_hl[8388608];   // cols-LSTM out NHWC (hi,lo) bf16x2
__device__ uint32_t g_hlB[8388608];       // conv temps, NHWC hl
__device__ uint32_t g_hlC[8388608];
__device__ uint32_t g_hlD[4194304];       // 128-channel temp
__device__ __nv_bfloat16 g_wb[11206656];  // conv weights: [ot][tap][cc][pass][k64][n128]
__device__ float    g_whhT[2][65536];
__device__ float    g_bias2[2][512];

// wb region offsets (elements)
#define WB_A 0u
#define WB_B 2359296u
#define WB_C 4718592u
#define WB_E 9437184u
#define WB_F 10616832u

// ===========================================================================
// mma.sync / ldmatrix helpers (legacy HMMA path — legal on compute_103)
// ===========================================================================
__device__ __forceinline__ uint32_t smem_u32(const void* p) {
    uint32_t a;
    asm("{ .reg .u64 t; cvta.to.shared.u64 t, %1; cvt.u32.u64 %0, t; }" : "=r"(a) : "l"(p));
    return a;
}
__device__ __forceinline__ void ldsm4(uint32_t* r, uint32_t addr) {
    asm volatile("ldmatrix.sync.aligned.m8n8.x4.shared.b16 {%0,%1,%2,%3}, [%4];"
        : "=r"(r[0]), "=r"(r[1]), "=r"(r[2]), "=r"(r[3]) : "r"(addr));
}
__device__ __forceinline__ void ldsm4t(uint32_t* r, uint32_t addr) {
    asm volatile("ldmatrix.sync.aligned.m8n8.x4.trans.shared.b16 {%0,%1,%2,%3}, [%4];"
        : "=r"(r[0]), "=r"(r[1]), "=r"(r[2]), "=r"(r[3]) : "r"(addr));
}
__device__ __forceinline__ void mma16816(float* c, const uint32_t* a, uint32_t b0, uint32_t b1) {
    asm volatile("mma.sync.aligned.m16n8k16.row.col.f32.bf16.bf16.f32 "
        "{%0,%1,%2,%3}, {%4,%5,%6,%7}, {%8,%9}, {%0,%1,%2,%3};"
        : "+f"(c[0]), "+f"(c[1]), "+f"(c[2]), "+f"(c[3])
        : "r"(a[0]), "r"(a[1]), "r"(a[2]), "r"(a[3]), "r"(b0), "r"(b1));
}
__device__ __forceinline__ uint32_t hl_pack(float v) {
    __nv_bfloat16 hi = __float2bfloat16(v);
    __nv_bfloat16 lo = __float2bfloat16(v - __bfloat162float(hi));
    return (uint32_t)__bfloat16_as_ushort(hi) | ((uint32_t)__bfloat16_as_ushort(lo) << 16);
}

// ===========================================================================
// prep: Whh transpose, bias sums, bf16 hi/lo weight tiles in staging layout
// layout: [ot][tap][cc][pass(2)][k(64)][n(128)] bf16 ; k=2c+{0,1} within chunk
//   pass0: B[2c]=B[2c+1]=w_hi ; pass1: B[2c]=w_lo, B[2c+1]=0
// ===========================================================================
__global__ void prep_kernel(const float* __restrict__ whh_f, const float* __restrict__ whh_b,
                            const float* __restrict__ bih_f, const float* __restrict__ bhh_f,
                            const float* __restrict__ bih_b, const float* __restrict__ bhh_b,
                            const float* __restrict__ c2w1, const float* __restrict__ c2w2,
                            const float* __restrict__ cvw1, const float* __restrict__ cvw2)
{
    unsigned i = blockIdx.x * 256u + threadIdx.x;
    if (i < 512u * 128u) {
        int g = i / 128, k = i % 128;
        g_whhT[0][k * 512 + g] = whh_f[i];
        g_whhT[1][k * 512 + g] = whh_b[i];
    }
    if (i < 512u) {
        g_bias2[0][i] = bih_f[i] + bhh_f[i];
        g_bias2[1][i] = bih_b[i] + bhh_b[i];
    }
    if (i < 11206656u) {
        unsigned l; int CC; int kind;
        if      (i < WB_B) { l = i - WB_A; CC = 8;  kind = 0; }
        else if (i < WB_C) { l = i - WB_B; CC = 8;  kind = 1; }
        else if (i < WB_E) { l = i - WB_C; CC = 16; kind = 2; }
        else if (i < WB_F) { l = i - WB_E; CC = 8;  kind = 3; }
        else               { l = i - WB_F; CC = 4;  kind = 4; }
        int n    = l & 127;
        int k    = (l >> 7) & 63;
        int pass = (l >> 13) & 1;
        unsigned q = l >> 14;
        int cc  = q % CC;  q /= CC;
        int tap = q % 9;   q /= 9;
        int ot  = q;
        int c  = cc * 32 + (k >> 1);
        int oc = ot * 128 + n;
        int odd = k & 1;
        float w;
        if      (kind == 0) w = c2w1[((size_t)oc * 512 + c) * 9 + tap]
                              + c2w1[((size_t)oc * 512 + c + 256) * 9 + tap];
        else if (kind == 1) w = c2w2[((size_t)oc * 256 + c) * 9 + tap];
        else if (kind == 2) w = c2w1[((size_t)oc * 512 + c) * 9 + tap];
        else if (kind == 3) w = cvw1[((size_t)oc * 256 + c) * 9 + tap];
        else                w = cvw2[((size_t)oc * 128 + c) * 9 + tap];
        __nv_bfloat16 hi = __float2bfloat16(w);
        __nv_bfloat16 val;
        if (pass == 0) val = hi;
        else val = odd ? __float2bfloat16(0.f)
                       : __float2bfloat16(w - __bfloat162float(hi));
        g_wb[i] = val;
    }
}

// ===========================================================================
// build rows-sequence (upsample + concat, NHWC fp32)
// ===========================================================================
__global__ __launch_bounds__(256) void build_seq_kernel(const float* __restrict__ x2,
                                                        const float* __restrict__ x1)
{
    __shared__ float sh[32][65];
    int bh = blockIdx.x;
    int b = bh >> 6, h = bh & 63;
    int ct = blockIdx.y;
    int c0 = ct * 32;
    int tid = threadIdx.x;

    if (ct < 4) {
        for (int idx = tid; idx < 32 * 64; idx += 256) {
            int ci = idx >> 6, w = idx & 63;
            sh[ci][w] = x2[(((size_t)b * 128 + (c0 + ci)) * 64 + h) * 64 + w];
        }
    } else {
        int cc0 = c0 - 128;
        float py = (float)h * 31.0f / 63.0f;
        int yl = (int)floorf(py);
        float wy = py - (float)yl;
        int yh = min(yl + 1, 31);
        for (int idx = tid; idx < 32 * 64; idx += 256) {
            int ci = idx >> 6, w = idx & 63;
            float px = (float)w * 31.0f / 63.0f;
            int xl = (int)floorf(px);
            float wx = px - (float)xl;
            int xh = min(xl + 1, 31);
            const float* base = x1 + ((size_t)b * 128 + (cc0 + ci)) * 1024;
            float v00 = base[yl * 32 + xl], v01 = base[yl * 32 + xh];
            float v10 = base[yh * 32 + xl], v11 = base[yh * 32 + xh];
            float v0 = v00 * (1.f - wx) + v01 * wx;
            float v1 = v10 * (1.f - wx) + v11 * wx;
            sh[ci][w] = v0 * (1.f - wy) + v1 * wy;
        }
    }
    __syncthreads();
    for (int idx = tid; idx < 32 * 64; idx += 256) {
        int w = idx >> 5, cl = idx & 31;
        g_seq[((size_t)bh * 64 + w) * 256 + c0 + cl] = sh[cl][w];
    }
}

// ===========================================================================
// GEMM: xg[32768,1024] = A[32768,256] @ [Wih_f;Wih_b]^T + bias  (scalar fp32)
// ===========================================================================
__global__ __launch_bounds__(256) void gemm_xg_kernel(int mode,
                                                      const float* __restrict__ wih_f,
                                                      const float* __restrict__ wih_b)
{
    const float* A = mode ? g_rows : g_seq;
    int mbase = blockIdx.x * 128;
    int nbase = blockIdx.y * 64;
    const float* Wg;
    const float* bias;
    int nloc;
    if (nbase < 512) { Wg = wih_f; bias = g_bias2[0]; nloc = nbase; }
    else             { Wg = wih_b; bias = g_bias2[1]; nloc = nbase - 512; }

    __shared__ __align__(16) float a_sh[16][132];
    __shared__ __align__(16) float b_sh[16][68];

    int tid = threadIdx.x;
    int tm = tid >> 4;
    int tn = tid & 15;
    int lma = tid >> 1;
    int lka = (tid & 1) * 8;
    int lmb = tid >> 2;
    int lkb = (tid & 3) * 4;

    float acc[8][4];
#pragma unroll
    for (int i = 0; i < 8; i++)
#pragma unroll
        for (int j = 0; j < 4; j++) acc[i][j] = 0.f;

    for (int k0 = 0; k0 < 256; k0 += 16) {
        float4 va0 = *(const float4*)&A [((size_t)(mbase + lma)) * 256 + k0 + lka];
        float4 va1 = *(const float4*)&A [((size_t)(mbase + lma)) * 256 + k0 + lka + 4];
        float4 vb  = *(const float4*)&Wg[((size_t)(nloc + lmb)) * 256 + k0 + lkb];
        a_sh[lka + 0][lma] = va0.x; a_sh[lka + 1][lma] = va0.y;
        a_sh[lka + 2][lma] = va0.z; a_sh[lka + 3][lma] = va0.w;
        a_sh[lka + 4][lma] = va1.x; a_sh[lka + 5][lma] = va1.y;
        a_sh[lka + 6][lma] = va1.z; a_sh[lka + 7][lma] = va1.w;
        b_sh[lkb + 0][lmb] = vb.x;  b_sh[lkb + 1][lmb] = vb.y;
        b_sh[lkb + 2][lmb] = vb.z;  b_sh[lkb + 3][lmb] = vb.w;
        __syncthreads();
#pragma unroll
        for (int k = 0; k < 16; k++) {
            float4 a0 = *(const float4*)&a_sh[k][tm * 8];
            float4 a1 = *(const float4*)&a_sh[k][tm * 8 + 4];
            float4 b4 = *(const float4*)&b_sh[k][tn * 4];
            float av[8] = {a0.x, a0.y, a0.z, a0.w, a1.x, a1.y, a1.z, a1.w};
            float bv[4] = {b4.x, b4.y, b4.z, b4.w};
#pragma unroll
            for (int i = 0; i < 8; i++)
#pragma unroll
                for (int j = 0; j < 4; j++) acc[i][j] += av[i] * bv[j];
        }
        __syncthreads();
    }
    float4 bb = *(const float4*)&bias[nloc + tn * 4];
    float bv[4] = {bb.x, bb.y, bb.z, bb.w};
#pragma unroll
    for (int i = 0; i < 8; i++) {
        float* dst = &g_xg[(size_t)(mbase + tm * 8 + i) * 1024 + nbase + tn * 4];
        *(float4*)dst = make_float4(acc[i][0] + bv[0], acc[i][1] + bv[1],
                                    acc[i][2] + bv[2], acc[i][3] + bv[3]);
    }
}

// ===========================================================================
// LSTM recurrence: 256 threads, 8 seqs/block, 64 steps, xg prefetch.
// mode 0 -> g_rows (fp32 [b][w][h][c]); mode 1 -> g_cols_hl (NHWC hi/lo pack)
// ===========================================================================
__global__ __launch_bounds__(256) void lstm_kernel(int mode)
{
    int dir = blockIdx.x >> 6;
    int blk = blockIdx.x & 63;
    const float* whhT = g_whhT[dir];
    const float* xg = g_xg + dir * 512;

    __shared__ __align__(16) float h_sh[8][132];
    __shared__ __align__(16) float g_sh[8][516];

    int tid = threadIdx.x;
    int ts = tid >> 7;
    int tg = tid & 127;
    int g0 = tg * 4;
    int s_base = ts * 4;
    int base_n = blk * 8;

    float c_reg[4] = {0.f, 0.f, 0.f, 0.f};

    float4 cur[4];
#pragma unroll
    for (int si = 0; si < 4; si++) {
        int n = base_n + s_base + si;
        int ta0 = dir ? 63 : 0;
        cur[si] = *(const float4*)&xg[((size_t)n * 64 + ta0) * 1024 + g0];
    }

    for (int t = 0; t < 64; t++) {
        int ta = dir ? (63 - t) : t;
        float acc[4][4];
#pragma unroll
        for (int si = 0; si < 4; si++) {
            acc[si][0] = cur[si].x; acc[si][1] = cur[si].y;
            acc[si][2] = cur[si].z; acc[si][3] = cur[si].w;
        }
        if (t < 63) {
            int tn = dir ? (62 - t) : (t + 1);
#pragma unroll
            for (int si = 0; si < 4; si++) {
                int n = base_n + s_base + si;
                cur[si] = *(const float4*)&xg[((size_t)n * 64 + tn) * 1024 + g0];
            }
        }
        if (t > 0) {
            for (int k0 = 0; k0 < 128; k0 += 4) {
                float4 h4[4];
#pragma unroll
                for (int si = 0; si < 4; si++)
                    h4[si] = *(const float4*)&h_sh[s_base + si][k0];
                const float* hp0 = (const float*)&h4[0];
                const float* hp1 = (const float*)&h4[1];
                const float* hp2 = (const float*)&h4[2];
                const float* hp3 = (const float*)&h4[3];
#pragma unroll
                for (int kk = 0; kk < 4; kk++) {
                    float4 w = *(const float4*)&whhT[((k0 + kk) << 9) + g0];
                    float h0 = hp0[kk], h1 = hp1[kk], h2 = hp2[kk], h3 = hp3[kk];
                    acc[0][0] += h0 * w.x; acc[0][1] += h0 * w.y; acc[0][2] += h0 * w.z; acc[0][3] += h0 * w.w;
                    acc[1][0] += h1 * w.x; acc[1][1] += h1 * w.y; acc[1][2] += h1 * w.z; acc[1][3] += h1 * w.w;
                    acc[2][0] += h2 * w.x; acc[2][1] += h2 * w.y; acc[2][2] += h2 * w.z; acc[2][3] += h2 * w.w;
                    acc[3][0] += h3 * w.x; acc[3][1] += h3 * w.y; acc[3][2] += h3 * w.z; acc[3][3] += h3 * w.w;
                }
            }
        }
#pragma unroll
        for (int si = 0; si < 4; si++) {
            *(float4*)&g_sh[s_base + si][g0] =
                make_float4(acc[si][0], acc[si][1], acc[si][2], acc[si][3]);
        }
        __syncthreads();
#pragma unroll
        for (int p = 0; p < 4; p++) {
            int idx = tid + p * 256;
            int s = idx >> 7, j = idx & 127;
            float iv = g_sh[s][j];
            float fv = g_sh[s][128 + j];
            float gv = g_sh[s][256 + j];
            float ov = g_sh[s][384 + j];
            float ig = 1.f / (1.f + expf(-iv));
            float fg = 1.f / (1.f + expf(-fv));
            float og = 1.f / (1.f + expf(-ov));
            c_reg[p] = fg * c_reg[p] + ig * tanhf(gv);
            float h = og * tanhf(c_reg[p]);
            h_sh[s][j] = h;
            int n = base_n + s;
            int b = n >> 6, loc = n & 63;
            if (mode == 0) {
                g_rows[(((size_t)(b * 64 + ta)) * 64 + loc) * 256 + dir * 128 + j] = h;
            } else {
                g_cols_hl[(((size_t)(b * 64 + ta)) * 64 + loc) * 256 + dir * 128 + j] = hl_pack(h);
            }
        }
        __syncthreads();
    }
}

// ===========================================================================
// mma.sync bf16 implicit-GEMM 3x3 conv.
// CTA: 128 px (2 rows x 64) x 128 oc. 256 threads = 8 warps (4 M x 2 N).
// Input NHWC uint32 (bf16 hi|lo): packed word == two consecutive K entries.
// 2 passes per 32-channel chunk: B_hi (dup) then [B_lo, 0].
// ===========================================================================
__global__ __launch_bounds__(256, 2) void conv_mma_kernel(
    const uint32_t* __restrict__ in0, int C0,
    const uint32_t* __restrict__ in1, int C1,
    unsigned wb_off,
    const float* __restrict__ gamma, const float* __restrict__ beta,
    void* outp, int OC, int final_nchw)
{
    __shared__ __align__(16) char a_sh[128 * 144];   // [px][64 bf16], 144B stride
    __shared__ __align__(16) char b_sh[64 * 272];    // [k][128 bf16], 272B stride
    __shared__ float scs[128], bbs[128];

    int tid = threadIdx.x;
    int lane = tid & 31, wid = tid >> 5;
    int warp_m = wid & 3, warp_n = wid >> 2;
    int bx = blockIdx.x;
    int b = bx >> 5, y0 = (bx & 31) * 2;
    int ot = blockIdx.y, ocb = ot * 128;
    int CIN = C0 + C1, CC = CIN >> 5;

    if (tid < 128) {
        scs[tid] = gamma[ocb + tid] * rsqrtf(1.f + EPS_BN);
        bbs[tid] = beta[ocb + tid];
    }

    float acc[2][8][4];
#pragma unroll
    for (int m = 0; m < 2; m++)
#pragma unroll
        for (int j = 0; j < 8; j++)
#pragma unroll
            for (int q = 0; q < 4; q++) acc[m][j][q] = 0.f;

    uint32_t a_base = smem_u32(a_sh);
    uint32_t b_base = smem_u32(b_sh);

    // ldmatrix lane addresses
    int arow = warp_m * 32 + (lane & 7) + ((lane >> 3) & 1) * 8;
    uint32_t a_addr0 = a_base + arow * 144 + ((lane >> 4) * 16);
    int brow = (lane & 7) + ((lane >> 3) & 1) * 8;
    int bcol = warp_n * 64 + ((lane >> 4) * 8);
    uint32_t b_addr0 = b_base + brow * 272 + bcol * 2;

    // A staging indices
    int s_px = tid >> 1, s_half = tid & 1;
    int s_yo = s_px >> 6, s_x = s_px & 63;

    for (int tap = 0; tap < 9; tap++) {
        int ty = tap / 3 - 1, tx = tap % 3 - 1;
        int ys = y0 + s_yo + ty;
        int xs = s_x + tx;
        bool ok = ((unsigned)ys < 64u) && ((unsigned)xs < 64u);
        for (int cc = 0; cc < CC; cc++) {
            // ---- stage A (straight copy of hl words) ----
            {
                int c0 = cc * 32 + s_half * 16;
                const uint4* src;
                if (c0 < C0) src = (const uint4*)(in0 + ((size_t)((b * 64 + ys) * 64 + xs)) * C0 + c0);
                else         src = (const uint4*)(in1 + ((size_t)((b * 64 + ys) * 64 + xs)) * C1 + (c0 - C0));
                uint4* dst = (uint4*)(a_sh + s_px * 144 + s_half * 64);
#pragma unroll
                for (int i = 0; i < 4; i++) {
                    uint4 v = make_uint4(0u, 0u, 0u, 0u);
                    if (ok) v = src[i];
                    dst[i] = v;
                }
            }
            const uint4* wsrc = (const uint4*)(g_wb + wb_off +
                ((size_t)((ot * 9 + tap) * CC + cc)) * 16384u);
            // ---- stage B pass 0 (64 k-rows x 128 n = 1024 uint4) ----
#pragma unroll
            for (int i = 0; i < 4; i++) {
                int idx = tid + i * 256;
                *(uint4*)(b_sh + (idx >> 4) * 272 + (idx & 15) * 16) = wsrc[idx];
            }
            __syncthreads();
            // ---- compute pass 0 ----
#pragma unroll
            for (int ksub = 0; ksub < 4; ksub++) {
                uint32_t a0[4], a1[4];
                ldsm4(a0, a_addr0 + ksub * 32);
                ldsm4(a1, a_addr0 + 16 * 144 + ksub * 32);
                uint32_t bfr[4][4];
#pragma unroll
                for (int p = 0; p < 4; p++)
                    ldsm4t(bfr[p], b_addr0 + ksub * 16 * 272 + p * 32);
#pragma unroll
                for (int j = 0; j < 8; j++) {
                    uint32_t bq0 = bfr[j >> 1][(j & 1) * 2];
                    uint32_t bq1 = bfr[j >> 1][(j & 1) * 2 + 1];
                    mma16816(acc[0][j], a0, bq0, bq1);
                    mma16816(acc[1][j], a1, bq0, bq1);
                }
            }
            __syncthreads();
            // ---- stage B pass 1 ----
#pragma unroll
            for (int i = 0; i < 4; i++) {
                int idx = tid + i * 256;
                *(uint4*)(b_sh + (idx >> 4) * 272 + (idx & 15) * 16) = wsrc[1024 + idx];
            }
            __syncthreads();
            // ---- compute pass 1 ----
#pragma unroll
            for (int ksub = 0; ksub < 4; ksub++) {
                uint32_t a0[4], a1[4];
                ldsm4(a0, a_addr0 + ksub * 32);
                ldsm4(a1, a_addr0 + 16 * 144 + ksub * 32);
                uint32_t bfr[4][4];
#pragma unroll
                for (int p = 0; p < 4; p++)
                    ldsm4t(bfr[p], b_addr0 + ksub * 16 * 272 + p * 32);
#pragma unroll
                for (int j = 0; j < 8; j++) {
                    uint32_t bq0 = bfr[j >> 1][(j & 1) * 2];
                    uint32_t bq1 = bfr[j >> 1][(j & 1) * 2 + 1];
                    mma16816(acc[0][j], a0, bq0, bq1);
                    mma16816(acc[1][j], a1, bq0, bq1);
                }
            }
            __syncthreads();
        }
    }

    // ---- epilogue: scale + bias + relu, write out ----
#pragma unroll
    for (int m = 0; m < 2; m++) {
        int px0 = warp_m * 32 + m * 16 + (lane >> 2);
#pragma unroll
        for (int j = 0; j < 8; j++) {
            int oc = warp_n * 64 + j * 8 + (lane & 3) * 2;
            float sc0 = scs[oc], sc1 = scs[oc + 1];
            float bb0 = bbs[oc], bb1 = bbs[oc + 1];
            float v00 = fmaxf(fmaf(acc[m][j][0], sc0, bb0), 0.f);
            float v01 = fmaxf(fmaf(acc[m][j][1], sc1, bb1), 0.f);
            float v10 = fmaxf(fmaf(acc[m][j][2], sc0, bb0), 0.f);
            float v11 = fmaxf(fmaf(acc[m][j][3], sc1, bb1), 0.f);
            if (!final_nchw) {
                uint32_t* out = (uint32_t*)outp;
                size_t base0 = ((size_t)((b * 64 + (y0 + (px0 >> 6))) * 64 + (px0 & 63))) * OC + ocb + oc;
                int px1 = px0 + 8;
                size_t base1 = ((size_t)((b * 64 + (y0 + (px1 >> 6))) * 64 + (px1 & 63))) * OC + ocb + oc;
                *(uint2*)(out + base0) = make_uint2(hl_pack(v00), hl_pack(v01));
                *(uint2*)(out + base1) = make_uint2(hl_pack(v10), hl_pack(v11));
            } else {
                float* out = (float*)outp;
                size_t r0 = ((size_t)b * OC + ocb + oc) * 4096 + y0 * 64;
                size_t r1 = ((size_t)b * OC + ocb + oc + 1) * 4096 + y0 * 64;
                out[r0 + px0] = v00;
                out[r1 + px0] = v01;
                out[r0 + px0 + 8] = v10;
                out[r1 + px0 + 8] = v11;
            }
        }
    }
}

// ===========================================================================
// launcher
// ===========================================================================
extern "C" void kernel_launch(void* const* d_in, const int* in_sizes, int n_in,
                              void* d_out, int out_size)
{
    const float* x1    = (const float*)d_in[0];
    const float* x2    = (const float*)d_in[1];
    const float* wih_f = (const float*)d_in[2];
    const float* whh_f = (const float*)d_in[3];
    const float* bih_f = (const float*)d_in[4];
    const float* bhh_f = (const float*)d_in[5];
    const float* wih_b = (const float*)d_in[6];
    const float* whh_b = (const float*)d_in[7];
    const float* bih_b = (const float*)d_in[8];
    const float* bhh_b = (const float*)d_in[9];
    const float* c2_w1 = (const float*)d_in[10];
    const float* c2_g1 = (const float*)d_in[11];
    const float* c2_b1 = (const float*)d_in[12];
    const float* c2_w2 = (const float*)d_in[13];
    const float* c2_g2 = (const float*)d_in[14];
    const float* c2_b2 = (const float*)d_in[15];
    const float* cv_w1 = (const float*)d_in[16];
    const float* cv_g1 = (const float*)d_in[17];
    const float* cv_b1 = (const float*)d_in[18];
    const float* cv_w2 = (const float*)d_in[19];
    const float* cv_g2 = (const float*)d_in[20];
    const float* cv_b2 = (const float*)d_in[21];

    uint32_t *p_cols = nullptr, *p_hlB = nullptr, *p_hlC = nullptr, *p_hlD = nullptr;
    cudaGetSymbolAddress((void**)&p_cols, g_cols_hl);
    cudaGetSymbolAddress((void**)&p_hlB, g_hlB);
    cudaGetSymbolAddress((void**)&p_hlC, g_hlC);
    cudaGetSymbolAddress((void**)&p_hlD, g_hlD);

    prep_kernel<<<43776, 256>>>(whh_f, whh_b, bih_f, bhh_f, bih_b, bhh_b,
                                c2_w1, c2_w2, cv_w1, cv_w2);
    build_seq_kernel<<<dim3(512, 8), 256>>>(x2, x1);

    gemm_xg_kernel<<<dim3(256, 16), 256>>>(0, wih_f, wih_b);
    lstm_kernel<<<128, 256>>>(0);
    gemm_xg_kernel<<<dim3(256, 16), 256>>>(1, wih_f, wih_b);
    lstm_kernel<<<128, 256>>>(1);

    // x_site = double_conv(concat([x,x])) via folded weights (A), then c2_w2 (B)
    conv_mma_kernel<<<dim3(256, 2), 256>>>(p_cols, 256, nullptr, 0, WB_A,
                                           c2_g1, c2_b1, p_hlB, 256, 0);
    conv_mma_kernel<<<dim3(256, 2), 256>>>(p_hlB, 256, nullptr, 0, WB_B,
                                           c2_g2, c2_b2, p_hlC, 256, 0);
    // x = double_conv(concat([x, x_site]))
    conv_mma_kernel<<<dim3(256, 2), 256>>>(p_cols, 256, p_hlC, 256, WB_C,
                                           c2_g1, c2_b1, p_hlB, 256, 0);
    conv_mma_kernel<<<dim3(256, 2), 256>>>(p_hlB, 256, nullptr, 0, WB_B,
                                           c2_g2, c2_b2, p_hlC, 256, 0);
    // final double_conv (cv): 256->128, 128->128 -> d_out (fp32 NCHW)
    conv_mma_kernel<<<dim3(256, 1), 256>>>(p_hlC, 256, nullptr, 0, WB_E,
                                           cv_g1, cv_b1, p_hlD, 128, 0);
    conv_mma_kernel<<<dim3(256, 1), 256>>>(p_hlD, 128, nullptr, 0, WB_F,
                                           cv_g2, cv_b2, d_out, 128, 1);
}

// round 8
// speedup vs baseline: 2.0268x; 1.0835x over previous
#include <cuda_runtime.h>
#include <cuda_bf16.h>
#include <cstdint>
#include <math.h>

#define EPS_BN 1e-5f

// ===========================================================================
// scratch (device globals)
// ===========================================================================
__device__ float    g_seq [8388608];      // rows-LSTM input NHWC fp32
__device__ float    g_xg  [33554432];     // 32768 x 1024
__device__ float    g_rows[8388608];      // rows-LSTM out [b][w][h][c] fp32
__device__ uint32_t g_cols_hl[8388608];   // cols-LSTM out NHWC (hi,lo) bf16x2
__device__ uint32_t g_hlB[8388608];       // conv temps, NHWC hl
__device__ uint32_t g_hlC[8388608];
__device__ uint32_t g_hlD[4194304];       // 128-channel temp
__device__ __nv_bfloat16 g_wb[11206656];  // conv weights: [ot][tap][cc][pass][k64][n128]
__device__ float    g_whhT[2][65536];
__device__ float    g_bias2[2][512];

// wb region offsets (elements)
#define WB_A 0u
#define WB_B 2359296u
#define WB_C 4718592u
#define WB_E 9437184u
#define WB_F 10616832u

// ===========================================================================
// mma.sync / ldmatrix helpers (legacy HMMA path — legal on compute_103)
// ===========================================================================
__device__ __forceinline__ uint32_t smem_u32(const void* p) {
    uint32_t a;
    asm("{ .reg .u64 t; cvta.to.shared.u64 t, %1; cvt.u32.u64 %0, t; }" : "=r"(a) : "l"(p));
    return a;
}
__device__ __forceinline__ void ldsm4(uint32_t* r, uint32_t addr) {
    asm volatile("ldmatrix.sync.aligned.m8n8.x4.shared.b16 {%0,%1,%2,%3}, [%4];"
        : "=r"(r[0]), "=r"(r[1]), "=r"(r[2]), "=r"(r[3]) : "r"(addr));
}
__device__ __forceinline__ void ldsm4t(uint32_t* r, uint32_t addr) {
    asm volatile("ldmatrix.sync.aligned.m8n8.x4.trans.shared.b16 {%0,%1,%2,%3}, [%4];"
        : "=r"(r[0]), "=r"(r[1]), "=r"(r[2]), "=r"(r[3]) : "r"(addr));
}
__device__ __forceinline__ void mma16816(float* c, const uint32_t* a, uint32_t b0, uint32_t b1) {
    asm volatile("mma.sync.aligned.m16n8k16.row.col.f32.bf16.bf16.f32 "
        "{%0,%1,%2,%3}, {%4,%5,%6,%7}, {%8,%9}, {%0,%1,%2,%3};"
        : "+f"(c[0]), "+f"(c[1]), "+f"(c[2]), "+f"(c[3])
        : "r"(a[0]), "r"(a[1]), "r"(a[2]), "r"(a[3]), "r"(b0), "r"(b1));
}
__device__ __forceinline__ uint32_t hl_pack(float v) {
    __nv_bfloat16 hi = __float2bfloat16(v);
    __nv_bfloat16 lo = __float2bfloat16(v - __bfloat162float(hi));
    return (uint32_t)__bfloat16_as_ushort(hi) | ((uint32_t)__bfloat16_as_ushort(lo) << 16);
}

// ===========================================================================
// prep: Whh transpose, bias sums, bf16 hi/lo weight tiles in staging layout
// ===========================================================================
__global__ void prep_kernel(const float* __restrict__ whh_f, const float* __restrict__ whh_b,
                            const float* __restrict__ bih_f, const float* __restrict__ bhh_f,
                            const float* __restrict__ bih_b, const float* __restrict__ bhh_b,
                            const float* __restrict__ c2w1, const float* __restrict__ c2w2,
                            const float* __restrict__ cvw1, const float* __restrict__ cvw2)
{
    unsigned i = blockIdx.x * 256u + threadIdx.x;
    if (i < 512u * 128u) {
        int g = i / 128, k = i % 128;
        g_whhT[0][k * 512 + g] = whh_f[i];
        g_whhT[1][k * 512 + g] = whh_b[i];
    }
    if (i < 512u) {
        g_bias2[0][i] = bih_f[i] + bhh_f[i];
        g_bias2[1][i] = bih_b[i] + bhh_b[i];
    }
    if (i < 11206656u) {
        unsigned l; int CC; int kind;
        if      (i < WB_B) { l = i - WB_A; CC = 8;  kind = 0; }
        else if (i < WB_C) { l = i - WB_B; CC = 8;  kind = 1; }
        else if (i < WB_E) { l = i - WB_C; CC = 16; kind = 2; }
        else if (i < WB_F) { l = i - WB_E; CC = 8;  kind = 3; }
        else               { l = i - WB_F; CC = 4;  kind = 4; }
        int n    = l & 127;
        int k    = (l >> 7) & 63;
        int pass = (l >> 13) & 1;
        unsigned q = l >> 14;
        int cc  = q % CC;  q /= CC;
        int tap = q % 9;   q /= 9;
        int ot  = q;
        int c  = cc * 32 + (k >> 1);
        int oc = ot * 128 + n;
        int odd = k & 1;
        float w;
        if      (kind == 0) w = c2w1[((size_t)oc * 512 + c) * 9 + tap]
                              + c2w1[((size_t)oc * 512 + c + 256) * 9 + tap];
        else if (kind == 1) w = c2w2[((size_t)oc * 256 + c) * 9 + tap];
        else if (kind == 2) w = c2w1[((size_t)oc * 512 + c) * 9 + tap];
        else if (kind == 3) w = cvw1[((size_t)oc * 256 + c) * 9 + tap];
        else                w = cvw2[((size_t)oc * 128 + c) * 9 + tap];
        __nv_bfloat16 hi = __float2bfloat16(w);
        __nv_bfloat16 val;
        if (pass == 0) val = hi;
        else val = odd ? __float2bfloat16(0.f)
                       : __float2bfloat16(w - __bfloat162float(hi));
        g_wb[i] = val;
    }
}

// ===========================================================================
// build rows-sequence (upsample + concat, NHWC fp32)
// ===========================================================================
__global__ __launch_bounds__(256) void build_seq_kernel(const float* __restrict__ x2,
                                                        const float* __restrict__ x1)
{
    __shared__ float sh[32][65];
    int bh = blockIdx.x;
    int b = bh >> 6, h = bh & 63;
    int ct = blockIdx.y;
    int c0 = ct * 32;
    int tid = threadIdx.x;

    if (ct < 4) {
        for (int idx = tid; idx < 32 * 64; idx += 256) {
            int ci = idx >> 6, w = idx & 63;
            sh[ci][w] = x2[(((size_t)b * 128 + (c0 + ci)) * 64 + h) * 64 + w];
        }
    } else {
        int cc0 = c0 - 128;
        float py = (float)h * 31.0f / 63.0f;
        int yl = (int)floorf(py);
        float wy = py - (float)yl;
        int yh = min(yl + 1, 31);
        for (int idx = tid; idx < 32 * 64; idx += 256) {
            int ci = idx >> 6, w = idx & 63;
            float px = (float)w * 31.0f / 63.0f;
            int xl = (int)floorf(px);
            float wx = px - (float)xl;
            int xh = min(xl + 1, 31);
            const float* base = x1 + ((size_t)b * 128 + (cc0 + ci)) * 1024;
            float v00 = base[yl * 32 + xl], v01 = base[yl * 32 + xh];
            float v10 = base[yh * 32 + xl], v11 = base[yh * 32 + xh];
            float v0 = v00 * (1.f - wx) + v01 * wx;
            float v1 = v10 * (1.f - wx) + v11 * wx;
            sh[ci][w] = v0 * (1.f - wy) + v1 * wy;
        }
    }
    __syncthreads();
    for (int idx = tid; idx < 32 * 64; idx += 256) {
        int w = idx >> 5, cl = idx & 31;
        g_seq[((size_t)bh * 64 + w) * 256 + c0 + cl] = sh[cl][w];
    }
}

// ===========================================================================
// GEMM: xg[32768,1024] = A[32768,256] @ [Wih_f;Wih_b]^T + bias  (scalar fp32)
// ===========================================================================
__global__ __launch_bounds__(256) void gemm_xg_kernel(int mode,
                                                      const float* __restrict__ wih_f,
                                                      const float* __restrict__ wih_b)
{
    const float* A = mode ? g_rows : g_seq;
    int mbase = blockIdx.x * 128;
    int nbase = blockIdx.y * 64;
    const float* Wg;
    const float* bias;
    int nloc;
    if (nbase < 512) { Wg = wih_f; bias = g_bias2[0]; nloc = nbase; }
    else             { Wg = wih_b; bias = g_bias2[1]; nloc = nbase - 512; }

    __shared__ __align__(16) float a_sh[16][132];
    __shared__ __align__(16) float b_sh[16][68];

    int tid = threadIdx.x;
    int tm = tid >> 4;
    int tn = tid & 15;
    int lma = tid >> 1;
    int lka = (tid & 1) * 8;
    int lmb = tid >> 2;
    int lkb = (tid & 3) * 4;

    float acc[8][4];
#pragma unroll
    for (int i = 0; i < 8; i++)
#pragma unroll
        for (int j = 0; j < 4; j++) acc[i][j] = 0.f;

    for (int k0 = 0; k0 < 256; k0 += 16) {
        float4 va0 = *(const float4*)&A [((size_t)(mbase + lma)) * 256 + k0 + lka];
        float4 va1 = *(const float4*)&A [((size_t)(mbase + lma)) * 256 + k0 + lka + 4];
        float4 vb  = *(const float4*)&Wg[((size_t)(nloc + lmb)) * 256 + k0 + lkb];
        a_sh[lka + 0][lma] = va0.x; a_sh[lka + 1][lma] = va0.y;
        a_sh[lka + 2][lma] = va0.z; a_sh[lka + 3][lma] = va0.w;
        a_sh[lka + 4][lma] = va1.x; a_sh[lka + 5][lma] = va1.y;
        a_sh[lka + 6][lma] = va1.z; a_sh[lka + 7][lma] = va1.w;
        b_sh[lkb + 0][lmb] = vb.x;  b_sh[lkb + 1][lmb] = vb.y;
        b_sh[lkb + 2][lmb] = vb.z;  b_sh[lkb + 3][lmb] = vb.w;
        __syncthreads();
#pragma unroll
        for (int k = 0; k < 16; k++) {
            float4 a0 = *(const float4*)&a_sh[k][tm * 8];
            float4 a1 = *(const float4*)&a_sh[k][tm * 8 + 4];
            float4 b4 = *(const float4*)&b_sh[k][tn * 4];
            float av[8] = {a0.x, a0.y, a0.z, a0.w, a1.x, a1.y, a1.z, a1.w};
            float bv[4] = {b4.x, b4.y, b4.z, b4.w};
#pragma unroll
            for (int i = 0; i < 8; i++)
#pragma unroll
                for (int j = 0; j < 4; j++) acc[i][j] += av[i] * bv[j];
        }
        __syncthreads();
    }
    float4 bb = *(const float4*)&bias[nloc + tn * 4];
    float bv[4] = {bb.x, bb.y, bb.z, bb.w};
#pragma unroll
    for (int i = 0; i < 8; i++) {
        float* dst = &g_xg[(size_t)(mbase + tm * 8 + i) * 1024 + nbase + tn * 4];
        *(float4*)dst = make_float4(acc[i][0] + bv[0], acc[i][1] + bv[1],
                                    acc[i][2] + bv[2], acc[i][3] + bv[3]);
    }
}

// ===========================================================================
// LSTM recurrence: 256 blocks (dir = blk>>7), 4 seqs/block, 256 threads.
// Thread = 2 seq x 4 gates in the gate phase; 2 cells in activation phase.
// R1-style inner loop: per-k float4 LDG of whhT + scalar broadcast h from smem.
// ===========================================================================
__global__ __launch_bounds__(256) void lstm_kernel(int mode)
{
    int dir = blockIdx.x >> 7;
    int blk = blockIdx.x & 127;
    const float* whhT = g_whhT[dir];
    const float* xg = g_xg + dir * 512;

    __shared__ __align__(16) float h_sh[4][132];
    __shared__ __align__(16) float g_sh[4][516];

    int tid = threadIdx.x;
    int ts = tid >> 7;           // 0..1
    int tg = tid & 127;
    int g0 = tg * 4;
    int s_base = ts * 2;         // 2 sequences per thread
    int base_n = blk * 4;

    float c_reg[2] = {0.f, 0.f};

    for (int t = 0; t < 64; t++) {
        int ta = dir ? (63 - t) : t;
        float acc[2][4];
#pragma unroll
        for (int si = 0; si < 2; si++) {
            int n = base_n + s_base + si;
            float4 v = *(const float4*)&xg[((size_t)n * 64 + ta) * 1024 + g0];
            acc[si][0] = v.x; acc[si][1] = v.y; acc[si][2] = v.z; acc[si][3] = v.w;
        }
        if (t > 0) {
#pragma unroll 4
            for (int k = 0; k < 128; k++) {
                float4 w = *(const float4*)&whhT[(k << 9) + g0];
                float h0 = h_sh[s_base + 0][k];
                float h1 = h_sh[s_base + 1][k];
                acc[0][0] += h0 * w.x; acc[0][1] += h0 * w.y;
                acc[0][2] += h0 * w.z; acc[0][3] += h0 * w.w;
                acc[1][0] += h1 * w.x; acc[1][1] += h1 * w.y;
                acc[1][2] += h1 * w.z; acc[1][3] += h1 * w.w;
            }
        }
#pragma unroll
        for (int si = 0; si < 2; si++) {
            *(float4*)&g_sh[s_base + si][g0] =
                make_float4(acc[si][0], acc[si][1], acc[si][2], acc[si][3]);
        }
        __syncthreads();
#pragma unroll
        for (int p = 0; p < 2; p++) {
            int idx = tid + p * 256;
            int s = idx >> 7, j = idx & 127;
            float iv = g_sh[s][j];
            float fv = g_sh[s][128 + j];
            float gv = g_sh[s][256 + j];
            float ov = g_sh[s][384 + j];
            float ig = 1.f / (1.f + expf(-iv));
            float fg = 1.f / (1.f + expf(-fv));
            float og = 1.f / (1.f + expf(-ov));
            c_reg[p] = fg * c_reg[p] + ig * tanhf(gv);
            float h = og * tanhf(c_reg[p]);
            h_sh[s][j] = h;
            int n = base_n + s;
            int b = n >> 6, loc = n & 63;
            if (mode == 0) {
                g_rows[(((size_t)(b * 64 + ta)) * 64 + loc) * 256 + dir * 128 + j] = h;
            } else {
                g_cols_hl[(((size_t)(b * 64 + ta)) * 64 + loc) * 256 + dir * 128 + j] = hl_pack(h);
            }
        }
        __syncthreads();
    }
}

// ===========================================================================
// mma.sync bf16 implicit-GEMM 3x3 conv.
// CTA: 128 px (2 rows x 64) x 128 oc. 256 threads = 8 warps (4 M x 2 N).
// Both hi/lo B passes staged together -> 2 barriers per 32-channel chunk.
// Dynamic smem: A (18432 B) + B x2 passes (34816 B) = 53248 B.
// ===========================================================================
#define CONV_A_BYTES   (128 * 144)
#define CONV_B_BYTES   (64 * 272)
#define CONV_SMEM      (CONV_A_BYTES + 2 * CONV_B_BYTES)

__global__ __launch_bounds__(256, 2) void conv_mma_kernel(
    const uint32_t* __restrict__ in0, int C0,
    const uint32_t* __restrict__ in1, int C1,
    unsigned wb_off,
    const float* __restrict__ gamma, const float* __restrict__ beta,
    void* outp, int OC, int final_nchw)
{
    extern __shared__ __align__(16) char smem[];
    char* a_sh = smem;
    char* b_sh = smem + CONV_A_BYTES;
    __shared__ float scs[128], bbs[128];

    int tid = threadIdx.x;
    int lane = tid & 31, wid = tid >> 5;
    int warp_m = wid & 3, warp_n = wid >> 2;
    int bx = blockIdx.x;
    int b = bx >> 5, y0 = (bx & 31) * 2;
    int ot = blockIdx.y, ocb = ot * 128;
    int CIN = C0 + C1, CC = CIN >> 5;

    if (tid < 128) {
        scs[tid] = gamma[ocb + tid] * rsqrtf(1.f + EPS_BN);
        bbs[tid] = beta[ocb + tid];
    }

    float acc[2][8][4];
#pragma unroll
    for (int m = 0; m < 2; m++)
#pragma unroll
        for (int j = 0; j < 8; j++)
#pragma unroll
            for (int q = 0; q < 4; q++) acc[m][j][q] = 0.f;

    uint32_t a_base = smem_u32(a_sh);
    uint32_t b_base = smem_u32(b_sh);

    // ldmatrix lane addresses
    int arow = warp_m * 32 + (lane & 7) + ((lane >> 3) & 1) * 8;
    uint32_t a_addr0 = a_base + arow * 144 + ((lane >> 4) * 16);
    int brow = (lane & 7) + ((lane >> 3) & 1) * 8;
    int bcol = warp_n * 64 + ((lane >> 4) * 8);
    uint32_t b_addr0 = b_base + brow * 272 + bcol * 2;

    // A staging indices
    int s_px = tid >> 1, s_half = tid & 1;
    int s_yo = s_px >> 6, s_x = s_px & 63;

    for (int tap = 0; tap < 9; tap++) {
        int ty = tap / 3 - 1, tx = tap % 3 - 1;
        int ys = y0 + s_yo + ty;
        int xs = s_x + tx;
        bool ok = ((unsigned)ys < 64u) && ((unsigned)xs < 64u);
        for (int cc = 0; cc < CC; cc++) {
            // ---- stage A (straight copy of hl words) ----
            {
                int c0 = cc * 32 + s_half * 16;
                const uint4* src;
                if (c0 < C0) src = (const uint4*)(in0 + ((size_t)((b * 64 + ys) * 64 + xs)) * C0 + c0);
                else         src = (const uint4*)(in1 + ((size_t)((b * 64 + ys) * 64 + xs)) * C1 + (c0 - C0));
                uint4* dst = (uint4*)(a_sh + s_px * 144 + s_half * 64);
#pragma unroll
                for (int i = 0; i < 4; i++) {
                    uint4 v = make_uint4(0u, 0u, 0u, 0u);
                    if (ok) v = src[i];
                    dst[i] = v;
                }
            }
            // ---- stage B: BOTH passes (2048 uint4) ----
            const uint4* wsrc = (const uint4*)(g_wb + wb_off +
                ((size_t)((ot * 9 + tap) * CC + cc)) * 16384u);
#pragma unroll
            for (int i = 0; i < 8; i++) {
                int idx = tid + i * 256;
                int pofs = (idx >= 1024) ? CONV_B_BYTES : 0;
                int li = idx & 1023;
                *(uint4*)(b_sh + pofs + (li >> 4) * 272 + (li & 15) * 16) = wsrc[idx];
            }
            __syncthreads();
            // ---- compute both passes ----
#pragma unroll
            for (int pass = 0; pass < 2; pass++) {
                uint32_t bp = b_addr0 + pass * CONV_B_BYTES;
#pragma unroll
                for (int ksub = 0; ksub < 4; ksub++) {
                    uint32_t a0[4], a1[4];
                    ldsm4(a0, a_addr0 + ksub * 32);
                    ldsm4(a1, a_addr0 + 16 * 144 + ksub * 32);
                    uint32_t bfr[4][4];
#pragma unroll
                    for (int p = 0; p < 4; p++)
                        ldsm4t(bfr[p], bp + ksub * 16 * 272 + p * 32);
#pragma unroll
                    for (int j = 0; j < 8; j++) {
                        uint32_t bq0 = bfr[j >> 1][(j & 1) * 2];
                        uint32_t bq1 = bfr[j >> 1][(j & 1) * 2 + 1];
                        mma16816(acc[0][j], a0, bq0, bq1);
                        mma16816(acc[1][j], a1, bq0, bq1);
                    }
                }
            }
            __syncthreads();
        }
    }

    // ---- epilogue: scale + bias + relu, write out ----
#pragma unroll
    for (int m = 0; m < 2; m++) {
        int px0 = warp_m * 32 + m * 16 + (lane >> 2);
#pragma unroll
        for (int j = 0; j < 8; j++) {
            int oc = warp_n * 64 + j * 8 + (lane & 3) * 2;
            float sc0 = scs[oc], sc1 = scs[oc + 1];
            float bb0 = bbs[oc], bb1 = bbs[oc + 1];
            float v00 = fmaxf(fmaf(acc[m][j][0], sc0, bb0), 0.f);
            float v01 = fmaxf(fmaf(acc[m][j][1], sc1, bb1), 0.f);
            float v10 = fmaxf(fmaf(acc[m][j][2], sc0, bb0), 0.f);
            float v11 = fmaxf(fmaf(acc[m][j][3], sc1, bb1), 0.f);
            if (!final_nchw) {
                uint32_t* out = (uint32_t*)outp;
                size_t base0 = ((size_t)((b * 64 + (y0 + (px0 >> 6))) * 64 + (px0 & 63))) * OC + ocb + oc;
                int px1 = px0 + 8;
                size_t base1 = ((size_t)((b * 64 + (y0 + (px1 >> 6))) * 64 + (px1 & 63))) * OC + ocb + oc;
                *(uint2*)(out + base0) = make_uint2(hl_pack(v00), hl_pack(v01));
                *(uint2*)(out + base1) = make_uint2(hl_pack(v10), hl_pack(v11));
            } else {
                float* out = (float*)outp;
                size_t r0 = ((size_t)b * OC + ocb + oc) * 4096 + y0 * 64;
                size_t r1 = ((size_t)b * OC + ocb + oc + 1) * 4096 + y0 * 64;
                out[r0 + px0] = v00;
                out[r1 + px0] = v01;
                out[r0 + px0 + 8] = v10;
                out[r1 + px0 + 8] = v11;
            }
        }
    }
}

// ===========================================================================
// launcher
// ===========================================================================
extern "C" void kernel_launch(void* const* d_in, const int* in_sizes, int n_in,
                              void* d_out, int out_size)
{
    const float* x1    = (const float*)d_in[0];
    const float* x2    = (const float*)d_in[1];
    const float* wih_f = (const float*)d_in[2];
    const float* whh_f = (const float*)d_in[3];
    const float* bih_f = (const float*)d_in[4];
    const float* bhh_f = (const float*)d_in[5];
    const float* wih_b = (const float*)d_in[6];
    const float* whh_b = (const float*)d_in[7];
    const float* bih_b = (const float*)d_in[8];
    const float* bhh_b = (const float*)d_in[9];
    const float* c2_w1 = (const float*)d_in[10];
    const float* c2_g1 = (const float*)d_in[11];
    const float* c2_b1 = (const float*)d_in[12];
    const float* c2_w2 = (const float*)d_in[13];
    const float* c2_g2 = (const float*)d_in[14];
    const float* c2_b2 = (const float*)d_in[15];
    const float* cv_w1 = (const float*)d_in[16];
    const float* cv_g1 = (const float*)d_in[17];
    const float* cv_b1 = (const float*)d_in[18];
    const float* cv_w2 = (const float*)d_in[19];
    const float* cv_g2 = (const float*)d_in[20];
    const float* cv_b2 = (const float*)d_in[21];

    uint32_t *p_cols = nullptr, *p_hlB = nullptr, *p_hlC = nullptr, *p_hlD = nullptr;
    cudaGetSymbolAddress((void**)&p_cols, g_cols_hl);
    cudaGetSymbolAddress((void**)&p_hlB, g_hlB);
    cudaGetSymbolAddress((void**)&p_hlC, g_hlC);
    cudaGetSymbolAddress((void**)&p_hlD, g_hlD);

    cudaFuncSetAttribute(conv_mma_kernel,
                         cudaFuncAttributeMaxDynamicSharedMemorySize, CONV_SMEM);

    prep_kernel<<<43776, 256>>>(whh_f, whh_b, bih_f, bhh_f, bih_b, bhh_b,
                                c2_w1, c2_w2, cv_w1, cv_w2);
    build_seq_kernel<<<dim3(512, 8), 256>>>(x2, x1);

    gemm_xg_kernel<<<dim3(256, 16), 256>>>(0, wih_f, wih_b);
    lstm_kernel<<<256, 256>>>(0);
    gemm_xg_kernel<<<dim3(256, 16), 256>>>(1, wih_f, wih_b);
    lstm_kernel<<<256, 256>>>(1);

    // x_site = double_conv(concat([x,x])) via folded weights (A), then c2_w2 (B)
    conv_mma_kernel<<<dim3(256, 2), 256, CONV_SMEM>>>(p_cols, 256, nullptr, 0, WB_A,
                                                      c2_g1, c2_b1, p_hlB, 256, 0);
    conv_mma_kernel<<<dim3(256, 2), 256, CONV_SMEM>>>(p_hlB, 256, nullptr, 0, WB_B,
                                                      c2_g2, c2_b2, p_hlC, 256, 0);
    // x = double_conv(concat([x, x_site]))
    conv_mma_kernel<<<dim3(256, 2), 256, CONV_SMEM>>>(p_cols, 256, p_hlC, 256, WB_C,
                                                      c2_g1, c2_b1, p_hlB, 256, 0);
    conv_mma_kernel<<<dim3(256, 2), 256, CONV_SMEM>>>(p_hlB, 256, nullptr, 0, WB_B,
                                                      c2_g2, c2_b2, p_hlC, 256, 0);
    // final double_conv (cv): 256->128, 128->128 -> d_out (fp32 NCHW)
    conv_mma_kernel<<<dim3(256, 1), 256, CONV_SMEM>>>(p_hlC, 256, nullptr, 0, WB_E,
                                                      cv_g1, cv_b1, p_hlD, 128, 0);
    conv_mma_kernel<<<dim3(256, 1), 256, CONV_SMEM>>>(p_hlD, 128, nullptr, 0, WB_F,
                                                      cv_g2, cv_b2, d_out, 128, 1);
}